// round 2
// baseline (speedup 1.0000x reference)
#include <cuda_runtime.h>
#include <cuda_bf16.h>

// EdgePredictor: out[e] = relu(concat(x[row], x[col]) @ W1 + b1) @ W2 + b2
// Factorization: concat(x_r,x_c)@W1 = x_r@W1[:128] + x_c@W1[128:]
//   Stage 1 (per node):  A[n] = x[n]@W1_top + b1 ;  B[n] = x[n]@W1_bot
//   Stage 2 (per edge):  h = relu(A[row] + B[col]) ; out = h@W2 + b2

#define ND  128          // embed dim
#define NPB 16           // nodes per block (stage 1)
#define KC  32           // k-chunk (stage 1)
#define MAX_NODES 100000

__device__ float g_A[(size_t)MAX_NODES * ND];   // 51.2 MB
__device__ float g_B[(size_t)MAX_NODES * ND];   // 51.2 MB

// ---------------------------------------------------------------------------
// Stage 1: A = x @ W1[0:128,:] + b1 ; B = x @ W1[128:256,:]
// 128 threads (thread j = output column), 16 nodes per block, smem-tiled W.
// ---------------------------------------------------------------------------
__global__ __launch_bounds__(128) void precompute_kernel(
    const float* __restrict__ x,    // [nnodes, 128]
    const float* __restrict__ W1,   // [256, 128] row-major
    const float* __restrict__ b1,   // [128]
    int nnodes)
{
    __shared__ float xs[NPB][ND];   // 8 KB
    __shared__ float wt[KC][ND];    // 16 KB
    __shared__ float wb[KC][ND];    // 16 KB

    const int j  = threadIdx.x;          // 0..127
    const int n0 = blockIdx.x * NPB;

    // Load node rows into smem (coalesced: j contiguous)
    #pragma unroll
    for (int n = 0; n < NPB; n++) {
        int node = n0 + n;
        xs[n][j] = (node < nnodes) ? x[(size_t)node * ND + j] : 0.f;
    }

    float accA[NPB], accB[NPB];
    const float bj = b1[j];
    #pragma unroll
    for (int n = 0; n < NPB; n++) { accA[n] = bj; accB[n] = 0.f; }

    for (int k0 = 0; k0 < ND; k0 += KC) {
        __syncthreads();   // xs ready (iter 0) / previous compute done reading wt,wb
        #pragma unroll
        for (int r = 0; r < KC; r++) {
            wt[r][j] = W1[(size_t)(k0 + r) * ND + j];
            wb[r][j] = W1[(size_t)(128 + k0 + r) * ND + j];
        }
        __syncthreads();

        #pragma unroll
        for (int kk = 0; kk < KC; kk++) {
            const float wtv = wt[kk][j];
            const float wbv = wb[kk][j];
            #pragma unroll
            for (int n = 0; n < NPB; n++) {
                const float xv = xs[n][k0 + kk];   // smem broadcast
                accA[n] = fmaf(xv, wtv, accA[n]);
                accB[n] = fmaf(xv, wbv, accB[n]);
            }
        }
    }

    #pragma unroll
    for (int n = 0; n < NPB; n++) {
        int node = n0 + n;
        if (node < nnodes) {
            g_A[(size_t)node * ND + j] = accA[n];
            g_B[(size_t)node * ND + j] = accB[n];
        }
    }
}

// ---------------------------------------------------------------------------
// Stage 2: warp per edge. Lane l owns k = 4l..4l+3 (one float4 = whole 512B
// row covered by a single LDG.128 per gather). A,B are L2-resident (102 MB).
// edge_index is int32 (JAX downcasts int64 -> int32 without x64 mode).
// ---------------------------------------------------------------------------
__global__ __launch_bounds__(256) void edge_kernel(
    const int* __restrict__ ei,        // [2, E] int32
    const float* __restrict__ W2,      // [128, 2]
    const float* __restrict__ b2,      // [2]
    float* __restrict__ out,           // [E, 2]
    int E)
{
    __shared__ float w2a[ND];
    __shared__ float w2b[ND];
    const int tid = threadIdx.x;
    if (tid < ND) {
        w2a[tid] = W2[tid * 2 + 0];
        w2b[tid] = W2[tid * 2 + 1];
    }
    __syncthreads();

    const int   lane = tid & 31;
    const int   k    = lane << 2;
    const float wa0 = w2a[k], wa1 = w2a[k + 1], wa2 = w2a[k + 2], wa3 = w2a[k + 3];
    const float wb0 = w2b[k], wb1 = w2b[k + 1], wb2 = w2b[k + 2], wb3 = w2b[k + 3];
    const float b20 = b2[0], b21 = b2[1];

    const int warp = (blockIdx.x * blockDim.x + tid) >> 5;
    const int nw   = (gridDim.x * blockDim.x) >> 5;

    for (int e = warp; e < E; e += nw) {
        const int r = ei[e];
        const int c = ei[(size_t)E + e];

        const float4 a = *reinterpret_cast<const float4*>(g_A + (size_t)r * ND + k);
        const float4 b = *reinterpret_cast<const float4*>(g_B + (size_t)c * ND + k);

        const float h0 = fmaxf(a.x + b.x, 0.f);
        const float h1 = fmaxf(a.y + b.y, 0.f);
        const float h2 = fmaxf(a.z + b.z, 0.f);
        const float h3 = fmaxf(a.w + b.w, 0.f);

        float o0 = fmaf(h0, wa0, fmaf(h1, wa1, fmaf(h2, wa2, h3 * wa3)));
        float o1 = fmaf(h0, wb0, fmaf(h1, wb1, fmaf(h2, wb2, h3 * wb3)));

        #pragma unroll
        for (int off = 16; off > 0; off >>= 1) {
            o0 += __shfl_xor_sync(0xFFFFFFFFu, o0, off);
            o1 += __shfl_xor_sync(0xFFFFFFFFu, o1, off);
        }

        if (lane == 0) {
            *reinterpret_cast<float2*>(out + 2 * (size_t)e) =
                make_float2(o0 + b20, o1 + b21);
        }
    }
}

// ---------------------------------------------------------------------------
extern "C" void kernel_launch(void* const* d_in, const int* in_sizes, int n_in,
                              void* d_out, int out_size)
{
    const float* x  = (const float*)d_in[0];      // node_embed [N,128]
    const int*   ei = (const int*)d_in[1];        // edge_index [2,E] int32
    const float* W1 = (const float*)d_in[2];      // [256,128]
    const float* b1 = (const float*)d_in[3];      // [128]
    const float* W2 = (const float*)d_in[4];      // [128,2]
    const float* b2 = (const float*)d_in[5];      // [2]
    float*       out = (float*)d_out;             // [E,2]

    const int nnodes = in_sizes[0] / ND;
    const int E      = in_sizes[1] / 2;

    // Stage 1: per-node precompute
    const int blocks1 = (nnodes + NPB - 1) / NPB;
    precompute_kernel<<<blocks1, 128>>>(x, W1, b1, nnodes);

    // Stage 2: warp per edge (8 warps/block)
    int blocks2 = (E + 7) / 8;
    edge_kernel<<<blocks2, 256>>>(ei, W2, b2, out, E);
}

// round 4
// speedup vs baseline: 1.1267x; 1.1267x over previous
#include <cuda_runtime.h>
#include <cuda_bf16.h>
#include <cstdint>

// EdgePredictor, factorized:
//   Stage 0: prep  W' = [W1_top^T ; W1_bot^T] rearranged n-major, split bf16 hi/lo,
//            stored pre-swizzled for ldmatrix.
//   Stage 1: mma.sync bf16 GEMM  Y[100000,256] = Xhi*Whi + Xlo*Whi + Xhi*Wlo (fp32 acc)
//            g_A = Y[:,:128] + b1 ; g_B = Y[:,128:]
//   Stage 2: out[e] = relu(g_A[row] + g_B[col]) @ W2 + b2   (4 lanes/edge)
// (tcgen05 is NOT available: harness PTX targets plain sm_103.)

#define ND  128
#define MAX_NODES 100000
#define TILE_M 128

__device__ float g_A[(size_t)MAX_NODES * ND];   // 51.2 MB
__device__ float g_B[(size_t)MAX_NODES * ND];   // 51.2 MB
__device__ uint4 g_Whi[4096];   // 64 KB: W' hi image [n=256][k=128] bf16, swizzled
__device__ uint4 g_Wlo[4096];   // 64 KB: W' lo image

// SMEM layout (dynamic, 192.5 KB)
#define SM_WHI 0
#define SM_WLO 65536
#define SM_AHI 131072
#define SM_ALO 163840
#define SM_B1  196608
#define SMEM_TOTAL 197120

// XOR swizzle for 256-byte rows: chunk bits [4:6] ^= row bits [8:10]
#define SWZ(x) ((x) ^ (((x) >> 4) & 0x70))

static __device__ __forceinline__ uint32_t smem_u32(const void* p) {
    uint32_t a;
    asm("{ .reg .u64 t; cvta.to.shared.u64 t, %1; cvt.u32.u64 %0, t; }" : "=r"(a) : "l"(p));
    return a;
}

#define LDSM4(r, addr)                                                          \
    asm volatile("ldmatrix.sync.aligned.m8n8.x4.shared.b16 {%0,%1,%2,%3}, [%4];"\
        : "=r"((r)[0]), "=r"((r)[1]), "=r"((r)[2]), "=r"((r)[3]) : "r"(addr))

#define MMA16816(d, a, b)                                                       \
    asm volatile("mma.sync.aligned.m16n8k16.row.col.f32.bf16.bf16.f32 "         \
        "{%0,%1,%2,%3}, {%4,%5,%6,%7}, {%8,%9}, {%0,%1,%2,%3};"                 \
        : "+f"((d)[0]), "+f"((d)[1]), "+f"((d)[2]), "+f"((d)[3])                \
        : "r"((a)[0]), "r"((a)[1]), "r"((a)[2]), "r"((a)[3]),                   \
          "r"((b)[0]), "r"((b)[1]))

// ---------------------------------------------------------------------------
// Stage 0: W' hi/lo bf16 images. W'[n][k]: n<128 -> W1[k][n]; else W1[128+k][n-128]
// ---------------------------------------------------------------------------
__global__ void prep_w_kernel(const float* __restrict__ W1) {
    int i = blockIdx.x * blockDim.x + threadIdx.x;
    if (i >= 256 * 128) return;
    int n = i >> 7, k = i & 127;
    float w = (n < 128) ? W1[k * 128 + n] : W1[(128 + k) * 128 + (n - 128)];
    __nv_bfloat16 hi = __float2bfloat16(w);
    __nv_bfloat16 lo = __float2bfloat16(w - __bfloat162float(hi));
    uint32_t sw = SWZ((uint32_t)(n * 256 + k * 2));
    *(__nv_bfloat16*)((char*)g_Whi + sw) = hi;
    *(__nv_bfloat16*)((char*)g_Wlo + sw) = lo;
}

// ---------------------------------------------------------------------------
// Stage 1: persistent bf16 mma.sync GEMM. 512 threads, 16 warps (4m x 4n),
// CTA tile 128x256, warp tile 32x64. fp32 accum, 3-term split precision.
// ---------------------------------------------------------------------------
__global__ __launch_bounds__(512, 1) void gemm_kernel(
    const float* __restrict__ x, const float* __restrict__ b1,
    int nnodes, int ntiles)
{
    extern __shared__ char smem[];
    const uint32_t sb = smem_u32(smem);
    const int tid  = threadIdx.x;
    const int lane = tid & 31;
    const int w    = tid >> 5;
    const int warp_m = w & 3;    // 4 groups of 32 rows
    const int warp_n = w >> 2;   // 4 groups of 64 cols

    // Load W images (128 KB) + b1 into SMEM once
    {
        uint4* dhi = (uint4*)(smem + SM_WHI);
        uint4* dlo = (uint4*)(smem + SM_WLO);
        #pragma unroll 8
        for (int i = tid; i < 4096; i += 512) { dhi[i] = g_Whi[i]; dlo[i] = g_Wlo[i]; }
        if (tid < 128) ((float*)(smem + SM_B1))[tid] = b1[tid];
    }
    __syncthreads();

    // ldmatrix lane address components
    const int a_row = (lane & 15);            // within m16
    const int a_ko  = (lane >> 4) << 4;       // +16B for k8..15 chunk
    const int b_row = (lane & 7) + ((lane >> 4) << 3);   // n within n16
    const int b_ko  = ((lane >> 3) & 1) << 4;

    for (int tile = blockIdx.x; tile < ntiles; tile += gridDim.x) {
        const long base = (long)tile * TILE_M;

        // ---- load X tile (128x128 f32), split -> bf16 hi/lo, swizzled ----
        #pragma unroll
        for (int it = 0; it < 8; it++) {
            int idx = it * 512 + tid;         // 4096 float4
            int row = idx >> 5;
            int c4  = idx & 31;
            long node = base + row;
            float4 v = make_float4(0.f, 0.f, 0.f, 0.f);
            if (node < nnodes) v = __ldg((const float4*)(x + node * (long)ND) + c4);

            __nv_bfloat162 h01 = __floats2bfloat162_rn(v.x, v.y);
            __nv_bfloat162 h23 = __floats2bfloat162_rn(v.z, v.w);
            __nv_bfloat162 l01 = __floats2bfloat162_rn(v.x - __bfloat162float(h01.x),
                                                       v.y - __bfloat162float(h01.y));
            __nv_bfloat162 l23 = __floats2bfloat162_rn(v.z - __bfloat162float(h23.x),
                                                       v.w - __bfloat162float(h23.y));
            uint32_t sw = SWZ((uint32_t)(row * 256 + c4 * 8));
            uint2 hp, lp;
            hp.x = *(uint32_t*)&h01; hp.y = *(uint32_t*)&h23;
            lp.x = *(uint32_t*)&l01; lp.y = *(uint32_t*)&l23;
            *(uint2*)(smem + SM_AHI + sw) = hp;
            *(uint2*)(smem + SM_ALO + sw) = lp;
        }
        __syncthreads();

        // ---- compute: acc[2 mstep][8 nstep][4] ----
        float acc[2][8][4];
        #pragma unroll
        for (int ms = 0; ms < 2; ms++)
            #pragma unroll
            for (int ns = 0; ns < 8; ns++)
                #pragma unroll
                for (int e = 0; e < 4; e++) acc[ms][ns][e] = 0.f;

        #pragma unroll
        for (int ks = 0; ks < 8; ks++) {
            uint32_t ah[2][4], al[2][4], bv[16];
            uint32_t babyte[4];

            #pragma unroll
            for (int ms = 0; ms < 2; ms++) {
                uint32_t ab = SWZ((uint32_t)((warp_m * 32 + ms * 16 + a_row) * 256
                                             + ks * 32 + a_ko));
                LDSM4(ah[ms], sb + SM_AHI + ab);
                LDSM4(al[ms], sb + SM_ALO + ab);
            }
            #pragma unroll
            for (int bj = 0; bj < 4; bj++) {
                babyte[bj] = SWZ((uint32_t)((warp_n * 64 + bj * 16 + b_row) * 256
                                            + ks * 32 + b_ko));
                LDSM4(&bv[bj * 4], sb + SM_WHI + babyte[bj]);
            }
            #pragma unroll
            for (int ms = 0; ms < 2; ms++)
                #pragma unroll
                for (int ns = 0; ns < 8; ns++)
                    MMA16816(acc[ms][ns], ah[ms], &bv[ns * 2]);
            #pragma unroll
            for (int ms = 0; ms < 2; ms++)
                #pragma unroll
                for (int ns = 0; ns < 8; ns++)
                    MMA16816(acc[ms][ns], al[ms], &bv[ns * 2]);
            // reload B as lo
            #pragma unroll
            for (int bj = 0; bj < 4; bj++)
                LDSM4(&bv[bj * 4], sb + SM_WLO + babyte[bj]);
            #pragma unroll
            for (int ms = 0; ms < 2; ms++)
                #pragma unroll
                for (int ns = 0; ns < 8; ns++)
                    MMA16816(acc[ms][ns], ah[ms], &bv[ns * 2]);
        }
        __syncthreads();   // done reading smem; next iter may overwrite A tiles

        // ---- epilogue: d0,d1 -> (row, col..col+1); d2,d3 -> (row+8, ...) ----
        float* dstbase = (warp_n < 2) ? g_A : g_B;
        const int colbase = warp_n * 64 - ((warp_n >= 2) ? 128 : 0) + 2 * (lane & 3);
        const int rowbase = warp_m * 32 + (lane >> 2);
        const float* b1s = (const float*)(smem + SM_B1);

        #pragma unroll
        for (int ms = 0; ms < 2; ms++) {
            #pragma unroll
            for (int ns = 0; ns < 8; ns++) {
                const int col = colbase + ns * 8;
                float bias0 = 0.f, bias1 = 0.f;
                if (warp_n < 2) { bias0 = b1s[col]; bias1 = b1s[col + 1]; }
                long node0 = base + rowbase + ms * 16;
                if (node0 < nnodes)
                    *(float2*)(dstbase + node0 * (long)ND + col) =
                        make_float2(acc[ms][ns][0] + bias0, acc[ms][ns][1] + bias1);
                long node1 = node0 + 8;
                if (node1 < nnodes)
                    *(float2*)(dstbase + node1 * (long)ND + col) =
                        make_float2(acc[ms][ns][2] + bias0, acc[ms][ns][3] + bias1);
            }
        }
    }
}

// ---------------------------------------------------------------------------
// Stage 2: 4 lanes per edge, 8 edges per warp. Each lane: 32 k's = 8 float4
// pairs (16 independent LDG.128 in flight). 2-level shuffle reduce.
// ---------------------------------------------------------------------------
__global__ __launch_bounds__(256) void edge_kernel(
    const int* __restrict__ ei,        // [2, E] int32
    const float* __restrict__ W2,      // [128, 2]
    const float* __restrict__ b2,      // [2]
    float* __restrict__ out,           // [E, 2]
    int E)
{
    __shared__ float w2a[ND];
    __shared__ float w2b[ND];
    const int tid = threadIdx.x;
    if (tid < ND) {
        w2a[tid] = W2[tid * 2 + 0];
        w2b[tid] = W2[tid * 2 + 1];
    }
    __syncthreads();

    const int lane = tid & 31;
    const int t    = lane & 3;        // sub-lane within edge group
    const int sub  = lane >> 2;       // edge within warp (0..7)
    const float b20 = __ldg(b2), b21 = __ldg(b2 + 1);

    const int warp   = (blockIdx.x * blockDim.x + tid) >> 5;
    const int nwarps = (gridDim.x * blockDim.x) >> 5;

    for (int eb = warp * 8; eb < E; eb += nwarps * 8) {
        const int e = eb + sub;       // E % 8 == 0 -> valid when eb < E
        const int r = __ldg(ei + e);
        const int c = __ldg(ei + (size_t)E + e);

        const float4* pa = (const float4*)(g_A + (size_t)r * ND) + t * 8;
        const float4* pb = (const float4*)(g_B + (size_t)c * ND) + t * 8;
        const float4* wa = (const float4*)(w2a + t * 32);
        const float4* wb = (const float4*)(w2b + t * 32);

        float o0 = 0.f, o1 = 0.f;
        #pragma unroll
        for (int i = 0; i < 8; i++) {
            const float4 a  = __ldg(pa + i);
            const float4 b  = __ldg(pb + i);
            const float4 va = wa[i];
            const float4 vb = wb[i];
            const float h0 = fmaxf(a.x + b.x, 0.f);
            const float h1 = fmaxf(a.y + b.y, 0.f);
            const float h2 = fmaxf(a.z + b.z, 0.f);
            const float h3 = fmaxf(a.w + b.w, 0.f);
            o0 = fmaf(h0, va.x, fmaf(h1, va.y, fmaf(h2, va.z, fmaf(h3, va.w, o0))));
            o1 = fmaf(h0, vb.x, fmaf(h1, vb.y, fmaf(h2, vb.z, fmaf(h3, vb.w, o1))));
        }

        o0 += __shfl_xor_sync(0xFFFFFFFFu, o0, 1);
        o0 += __shfl_xor_sync(0xFFFFFFFFu, o0, 2);
        o1 += __shfl_xor_sync(0xFFFFFFFFu, o1, 1);
        o1 += __shfl_xor_sync(0xFFFFFFFFu, o1, 2);

        if (t == 0) {
            *(float2*)(out + 2 * (size_t)e) = make_float2(o0 + b20, o1 + b21);
        }
    }
}

// ---------------------------------------------------------------------------
extern "C" void kernel_launch(void* const* d_in, const int* in_sizes, int n_in,
                              void* d_out, int out_size)
{
    const float* x  = (const float*)d_in[0];      // [N,128]
    const int*   ei = (const int*)d_in[1];        // [2,E] int32
    const float* W1 = (const float*)d_in[2];      // [256,128]
    const float* b1 = (const float*)d_in[3];      // [128]
    const float* W2 = (const float*)d_in[4];      // [128,2]
    const float* b2 = (const float*)d_in[5];      // [2]
    float*       out = (float*)d_out;             // [E,2]

    const int nnodes = in_sizes[0] / ND;
    const int E      = in_sizes[1] / 2;
    const int ntiles = (nnodes + TILE_M - 1) / TILE_M;

    cudaFuncSetAttribute(gemm_kernel, cudaFuncAttributeMaxDynamicSharedMemorySize,
                         SMEM_TOTAL);

    prep_w_kernel<<<128, 256>>>(W1);
    gemm_kernel<<<148, 512, SMEM_TOTAL>>>(x, b1, nnodes, ntiles);
    edge_kernel<<<(E + 63) / 64, 256>>>(ei, W2, b2, out, E);
}

// round 5
// speedup vs baseline: 1.1991x; 1.0643x over previous
#include <cuda_runtime.h>
#include <cuda_bf16.h>
#include <cstdint>

// EdgePredictor, factorized:
//   Stage 0: prep  W' = [W1_top^T ; W1_bot^T] n-major, split bf16 hi/lo, pre-swizzled.
//   Stage 1: mma.sync bf16 GEMM  Y[100000,256] = Xhi*Whi + Xlo*Whi + Xhi*Wlo (fp32 acc)
//            cp.async software pipeline: stage X raw tile t+1 while computing tile t.
//            g_A = Y[:,:128] + b1 ; g_B = Y[:,128:]
//   Stage 2: out[e] = relu(g_A[row] + g_B[col]) @ W2 + b2   (4 lanes/edge)

#define ND  128
#define MAX_NODES 100000
#define TILE_M 64

__device__ float g_A[(size_t)MAX_NODES * ND];   // 51.2 MB
__device__ float g_B[(size_t)MAX_NODES * ND];   // 51.2 MB
__device__ uint4 g_Whi[4096];   // 64 KB: W' hi [n=256][k=128] bf16, swizzled
__device__ uint4 g_Wlo[4096];   // 64 KB

// SMEM layout (dynamic, 192.5 KB)
#define SM_WHI  0          // 65536
#define SM_WLO  65536      // 65536
#define SM_ARAW 131072     // 32768  raw fp32 X tile (64 x 128 f32), cp.async dest
#define SM_AHI  163840     // 16384  bf16 hi tile (64 x 128)
#define SM_ALO  180224     // 16384  bf16 lo tile
#define SM_B1   196608     // 512
#define SMEM_TOTAL 197120

// XOR swizzle for 256-byte rows: chunk bits [4:6] ^= row bits [8:10]
#define SWZ(x) ((x) ^ (((x) >> 4) & 0x70))

static __device__ __forceinline__ uint32_t smem_u32(const void* p) {
    uint32_t a;
    asm("{ .reg .u64 t; cvta.to.shared.u64 t, %1; cvt.u32.u64 %0, t; }" : "=r"(a) : "l"(p));
    return a;
}

#define LDSM4(r, addr)                                                          \
    asm volatile("ldmatrix.sync.aligned.m8n8.x4.shared.b16 {%0,%1,%2,%3}, [%4];"\
        : "=r"((r)[0]), "=r"((r)[1]), "=r"((r)[2]), "=r"((r)[3]) : "r"(addr))

#define MMA16816(d, a, b)                                                       \
    asm volatile("mma.sync.aligned.m16n8k16.row.col.f32.bf16.bf16.f32 "         \
        "{%0,%1,%2,%3}, {%4,%5,%6,%7}, {%8,%9}, {%0,%1,%2,%3};"                 \
        : "+f"((d)[0]), "+f"((d)[1]), "+f"((d)[2]), "+f"((d)[3])                \
        : "r"((a)[0]), "r"((a)[1]), "r"((a)[2]), "r"((a)[3]),                   \
          "r"((b)[0]), "r"((b)[1]))

#define CP_ASYNC16(dst, src, nbytes)                                            \
    asm volatile("cp.async.cg.shared.global [%0], [%1], 16, %2;"                \
        :: "r"(dst), "l"(src), "r"(nbytes))
#define CP_COMMIT() asm volatile("cp.async.commit_group;" ::: "memory")
#define CP_WAIT0()  asm volatile("cp.async.wait_group 0;" ::: "memory")

// ---------------------------------------------------------------------------
// Stage 0: W' hi/lo bf16 images. W'[n][k]: n<128 -> W1[k][n]; else W1[128+k][n-128]
// ---------------------------------------------------------------------------
__global__ void prep_w_kernel(const float* __restrict__ W1) {
    int i = blockIdx.x * blockDim.x + threadIdx.x;
    if (i >= 256 * 128) return;
    int n = i >> 7, k = i & 127;
    float w = (n < 128) ? W1[k * 128 + n] : W1[(128 + k) * 128 + (n - 128)];
    __nv_bfloat16 hi = __float2bfloat16(w);
    __nv_bfloat16 lo = __float2bfloat16(w - __bfloat162float(hi));
    uint32_t sw = SWZ((uint32_t)(n * 256 + k * 2));
    *(__nv_bfloat16*)((char*)g_Whi + sw) = hi;
    *(__nv_bfloat16*)((char*)g_Wlo + sw) = lo;
}

// ---------------------------------------------------------------------------
// Stage 1: persistent pipelined GEMM. 512 threads, 16 warps (2m x 8n),
// CTA tile 64x256, warp tile 32x32. cp.async stages next raw X tile under MMA.
// ---------------------------------------------------------------------------
__global__ __launch_bounds__(512, 1) void gemm_kernel(
    const float* __restrict__ x, const float* __restrict__ b1,
    int nnodes, int ntiles)
{
    extern __shared__ char smem[];
    const uint32_t sb = smem_u32(smem);
    const int tid  = threadIdx.x;
    const int lane = tid & 31;
    const int w    = tid >> 5;
    const int warp_m = w & 1;    // 2 groups of 32 rows
    const int warp_n = w >> 1;   // 8 groups of 32 cols

    // Load W images (128 KB) + b1 into SMEM once
    {
        uint4* dhi = (uint4*)(smem + SM_WHI);
        uint4* dlo = (uint4*)(smem + SM_WLO);
        #pragma unroll 8
        for (int i = tid; i < 4096; i += 512) { dhi[i] = g_Whi[i]; dlo[i] = g_Wlo[i]; }
        if (tid < 128) ((float*)(smem + SM_B1))[tid] = b1[tid];
    }

    // Per-thread staging coords: 2048 float4 per tile / 512 threads = 4 each.
    // iter it: idx4 = it*512 + tid ; row = idx4>>5 (0..63), c4 = idx4&31.
    const int prow = tid >> 5;          // row stride 16 per iter
    const int pc4  = tid & 31;

    // ldmatrix lane address components
    const int a_row = (lane & 15);
    const int a_ko  = (lane >> 4) << 4;
    const int b_row = (lane & 7) + ((lane >> 4) << 3);
    const int b_ko  = ((lane >> 3) & 1) << 4;

    // ---- prefetch first tile ----
    int tile = blockIdx.x;
    {
        long base = (long)tile * TILE_M;
        #pragma unroll
        for (int it = 0; it < 4; it++) {
            int row = prow + it * 16;
            long node = base + row;
            const char* src = (const char*)(x + node * (long)ND) + pc4 * 16;
            uint32_t dst = sb + SM_ARAW + row * 512 + pc4 * 16;
            int nb = (tile < ntiles && node < nnodes) ? 16 : 0;
            if (nb == 0) src = (const char*)x;      // safe address
            CP_ASYNC16(dst, src, nb);
        }
        CP_COMMIT();
    }
    CP_WAIT0();
    __syncthreads();

    for (; tile < ntiles; tile += gridDim.x) {
        const long base = (long)tile * TILE_M;

        // ---- convert staged raw tile -> bf16 hi/lo (swizzled) ----
        #pragma unroll
        for (int it = 0; it < 4; it++) {
            int row = prow + it * 16;
            float4 v = *(const float4*)(smem + SM_ARAW + row * 512 + pc4 * 16);
            __nv_bfloat162 h01 = __floats2bfloat162_rn(v.x, v.y);
            __nv_bfloat162 h23 = __floats2bfloat162_rn(v.z, v.w);
            __nv_bfloat162 l01 = __floats2bfloat162_rn(v.x - __bfloat162float(h01.x),
                                                       v.y - __bfloat162float(h01.y));
            __nv_bfloat162 l23 = __floats2bfloat162_rn(v.z - __bfloat162float(h23.x),
                                                       v.w - __bfloat162float(h23.y));
            uint32_t sw = SWZ((uint32_t)(row * 256 + pc4 * 8));
            uint2 hp, lp;
            hp.x = *(uint32_t*)&h01; hp.y = *(uint32_t*)&h23;
            lp.x = *(uint32_t*)&l01; lp.y = *(uint32_t*)&l23;
            *(uint2*)(smem + SM_AHI + sw) = hp;
            *(uint2*)(smem + SM_ALO + sw) = lp;
        }
        __syncthreads();   // Ahi/Alo ready; everyone done reading ARAW

        // ---- issue cp.async for next tile into ARAW (overlaps with MMA) ----
        {
            int nxt = tile + gridDim.x;
            long nbase = (long)nxt * TILE_M;
            #pragma unroll
            for (int it = 0; it < 4; it++) {
                int row = prow + it * 16;
                long node = nbase + row;
                const char* src = (const char*)(x + node * (long)ND) + pc4 * 16;
                uint32_t dst = sb + SM_ARAW + row * 512 + pc4 * 16;
                int nb = (nxt < ntiles && node < nnodes) ? 16 : 0;
                if (nb == 0) src = (const char*)x;
                CP_ASYNC16(dst, src, nb);
            }
            CP_COMMIT();
        }

        // ---- compute: acc[2 ms][4 ns][4] ----
        float acc[2][4][4];
        #pragma unroll
        for (int ms = 0; ms < 2; ms++)
            #pragma unroll
            for (int ns = 0; ns < 4; ns++)
                #pragma unroll
                for (int e = 0; e < 4; e++) acc[ms][ns][e] = 0.f;

        #pragma unroll
        for (int ks = 0; ks < 8; ks++) {
            uint32_t ah[2][4], al[2][4], bh[8], bl[8];
            #pragma unroll
            for (int ms = 0; ms < 2; ms++) {
                uint32_t ab = SWZ((uint32_t)((warp_m * 32 + ms * 16 + a_row) * 256
                                             + ks * 32 + a_ko));
                LDSM4(ah[ms], sb + SM_AHI + ab);
                LDSM4(al[ms], sb + SM_ALO + ab);
            }
            #pragma unroll
            for (int bj = 0; bj < 2; bj++) {
                uint32_t bb = SWZ((uint32_t)((warp_n * 32 + bj * 16 + b_row) * 256
                                             + ks * 32 + b_ko));
                LDSM4(&bh[bj * 4], sb + SM_WHI + bb);
                LDSM4(&bl[bj * 4], sb + SM_WLO + bb);
            }
            #pragma unroll
            for (int ms = 0; ms < 2; ms++) {
                #pragma unroll
                for (int ns = 0; ns < 4; ns++) {
                    MMA16816(acc[ms][ns], ah[ms], &bh[ns * 2]);   // hi*hi
                    MMA16816(acc[ms][ns], al[ms], &bh[ns * 2]);   // lo*hi
                    MMA16816(acc[ms][ns], ah[ms], &bl[ns * 2]);   // hi*lo
                }
            }
        }

        // ---- epilogue ----
        float* dstbase = (warp_n < 4) ? g_A : g_B;
        const int colbase = (warp_n & 3) * 32 + 2 * (lane & 3);
        const int rowbase = warp_m * 32 + (lane >> 2);
        const float* b1s = (const float*)(smem + SM_B1);

        #pragma unroll
        for (int ms = 0; ms < 2; ms++) {
            #pragma unroll
            for (int ns = 0; ns < 4; ns++) {
                const int col = colbase + ns * 8;
                float bias0 = 0.f, bias1 = 0.f;
                if (warp_n < 4) { bias0 = b1s[col]; bias1 = b1s[col + 1]; }
                long node0 = base + rowbase + ms * 16;
                if (node0 < nnodes)
                    *(float2*)(dstbase + node0 * (long)ND + col) =
                        make_float2(acc[ms][ns][0] + bias0, acc[ms][ns][1] + bias1);
                long node1 = node0 + 8;
                if (node1 < nnodes)
                    *(float2*)(dstbase + node1 * (long)ND + col) =
                        make_float2(acc[ms][ns][2] + bias0, acc[ms][ns][3] + bias1);
            }
        }

        CP_WAIT0();        // next raw tile landed
        __syncthreads();
    }
}

// ---------------------------------------------------------------------------
// Stage 2: 4 lanes per edge, 8 edges per warp. Each lane: 32 k's = 8 float4
// pairs (16 independent LDG.128 in flight). 2-level shuffle reduce.
// ---------------------------------------------------------------------------
__global__ __launch_bounds__(256) void edge_kernel(
    const int* __restrict__ ei,        // [2, E] int32
    const float* __restrict__ W2,      // [128, 2]
    const float* __restrict__ b2,      // [2]
    float* __restrict__ out,           // [E, 2]
    int E)
{
    __shared__ float w2a[ND];
    __shared__ float w2b[ND];
    const int tid = threadIdx.x;
    if (tid < ND) {
        w2a[tid] = W2[tid * 2 + 0];
        w2b[tid] = W2[tid * 2 + 1];
    }
    __syncthreads();

    const int lane = tid & 31;
    const int t    = lane & 3;
    const int sub  = lane >> 2;
    const float b20 = __ldg(b2), b21 = __ldg(b2 + 1);

    const int warp   = (blockIdx.x * blockDim.x + tid) >> 5;
    const int nwarps = (gridDim.x * blockDim.x) >> 5;

    for (int eb = warp * 8; eb < E; eb += nwarps * 8) {
        const int e = eb + sub;       // E % 8 == 0
        const int r = __ldg(ei + e);
        const int c = __ldg(ei + (size_t)E + e);

        const float4* pa = (const float4*)(g_A + (size_t)r * ND) + t * 8;
        const float4* pb = (const float4*)(g_B + (size_t)c * ND) + t * 8;
        const float4* wa = (const float4*)(w2a + t * 32);
        const float4* wb = (const float4*)(w2b + t * 32);

        float o0 = 0.f, o1 = 0.f;
        #pragma unroll
        for (int i = 0; i < 8; i++) {
            const float4 a  = __ldg(pa + i);
            const float4 b  = __ldg(pb + i);
            const float4 va = wa[i];
            const float4 vb = wb[i];
            const float h0 = fmaxf(a.x + b.x, 0.f);
            const float h1 = fmaxf(a.y + b.y, 0.f);
            const float h2 = fmaxf(a.z + b.z, 0.f);
            const float h3 = fmaxf(a.w + b.w, 0.f);
            o0 = fmaf(h0, va.x, fmaf(h1, va.y, fmaf(h2, va.z, fmaf(h3, va.w, o0))));
            o1 = fmaf(h0, vb.x, fmaf(h1, vb.y, fmaf(h2, vb.z, fmaf(h3, vb.w, o1))));
        }

        o0 += __shfl_xor_sync(0xFFFFFFFFu, o0, 1);
        o0 += __shfl_xor_sync(0xFFFFFFFFu, o0, 2);
        o1 += __shfl_xor_sync(0xFFFFFFFFu, o1, 1);
        o1 += __shfl_xor_sync(0xFFFFFFFFu, o1, 2);

        if (t == 0) {
            *(float2*)(out + 2 * (size_t)e) = make_float2(o0 + b20, o1 + b21);
        }
    }
}

// ---------------------------------------------------------------------------
extern "C" void kernel_launch(void* const* d_in, const int* in_sizes, int n_in,
                              void* d_out, int out_size)
{
    const float* x  = (const float*)d_in[0];      // [N,128]
    const int*   ei = (const int*)d_in[1];        // [2,E] int32
    const float* W1 = (const float*)d_in[2];      // [256,128]
    const float* b1 = (const float*)d_in[3];      // [128]
    const float* W2 = (const float*)d_in[4];      // [128,2]
    const float* b2 = (const float*)d_in[5];      // [2]
    float*       out = (float*)d_out;             // [E,2]

    const int nnodes = in_sizes[0] / ND;
    const int E      = in_sizes[1] / 2;
    const int ntiles = (nnodes + TILE_M - 1) / TILE_M;

    cudaFuncSetAttribute(gemm_kernel, cudaFuncAttributeMaxDynamicSharedMemorySize,
                         SMEM_TOTAL);

    prep_w_kernel<<<128, 256>>>(W1);
    gemm_kernel<<<148, 512, SMEM_TOTAL>>>(x, b1, nnodes, ntiles);
    edge_kernel<<<(E + 63) / 64, 256>>>(ei, W2, b2, out, E);
}